// round 2
// baseline (speedup 1.0000x reference)
#include <cuda_runtime.h>
#include <math.h>

#define NN 100000
#define HEADS 4
#define HID 16
#define F1 64          // HEADS*HID
#define NC 16
#define NEG 0.2f

// ---------------- scratch (device globals, no allocation) ----------------
__device__ __align__(128) float    g_h1[NN * F1];
__device__ __align__(128) float    g_as1[NN * HEADS];
__device__ __align__(128) float    g_ad1[NN * HEADS];
__device__ __align__(128) unsigned g_m1[NN * HEADS];   // enc-max, later float
__device__ __align__(128) float    g_den1[NN * HEADS];
__device__ __align__(128) float    g_acc1[NN * F1];
__device__ __align__(128) float    g_hw2[NN * NC];
__device__ __align__(128) float    g_as2[NN];
__device__ __align__(128) float    g_ad2[NN];
__device__ __align__(128) unsigned g_m2[NN];
__device__ __align__(128) float    g_den2[NN];
__device__ __align__(128) float    g_acc2[NN * NC];

// ---------------- helpers ----------------
__device__ __forceinline__ unsigned fenc(float f) {
    unsigned u = __float_as_uint(f);
    return (u & 0x80000000u) ? ~u : (u | 0x80000000u);
}
__device__ __forceinline__ float fdec(unsigned u) {
    u = (u & 0x80000000u) ? (u & 0x7fffffffu) : ~u;
    return __uint_as_float(u);
}
__device__ __forceinline__ float lrelu(float v) { return v >= 0.f ? v : NEG * v; }

__device__ __forceinline__ void red_add_v4(float* addr, float a, float b, float c, float d) {
    asm volatile("red.global.add.v4.f32 [%0], {%1,%2,%3,%4};"
                 :: "l"(addr), "f"(a), "f"(b), "f"(c), "f"(d) : "memory");
}

// ---------------- layer 1 GEMM: h1 = x @ W1  (N x 128 @ 128 x 64) ----------------
__global__ void gemm1_kernel(const float* __restrict__ x, const float* __restrict__ W1, int n) {
    extern __shared__ float sm[];
    float* As = sm;               // 64 x 128
    float* Bs = sm + 64 * 128;    // 128 x 64
    int tid = threadIdx.x;
    int row0 = blockIdx.x * 64;

    for (int i = tid; i < 64 * 32; i += 256) {
        int r = i >> 5, c4 = (i & 31) << 2;
        float4 v = make_float4(0.f, 0.f, 0.f, 0.f);
        int gr = row0 + r;
        if (gr < n) v = *(const float4*)(x + (size_t)gr * 128 + c4);
        *(float4*)(As + r * 128 + c4) = v;
    }
    for (int i = tid; i < 128 * 16; i += 256) {
        int r = i >> 4, c4 = (i & 15) << 2;
        *(float4*)(Bs + r * 64 + c4) = *(const float4*)(W1 + r * 64 + c4);
    }
    __syncthreads();

    int tx = tid & 15, ty = tid >> 4;
    float acc[4][4];
#pragma unroll
    for (int i = 0; i < 4; i++)
#pragma unroll
        for (int j = 0; j < 4; j++) acc[i][j] = 0.f;

#pragma unroll
    for (int k4 = 0; k4 < 128; k4 += 4) {
        float4 a[4], b[4];
#pragma unroll
        for (int i = 0; i < 4; i++) a[i] = *(float4*)(As + (ty * 4 + i) * 128 + k4);
#pragma unroll
        for (int kk = 0; kk < 4; kk++) b[kk] = *(float4*)(Bs + (size_t)(k4 + kk) * 64 + tx * 4);
#pragma unroll
        for (int kk = 0; kk < 4; kk++) {
            float4 bv = b[kk];
#pragma unroll
            for (int i = 0; i < 4; i++) {
                float av = (kk == 0) ? a[i].x : (kk == 1) ? a[i].y : (kk == 2) ? a[i].z : a[i].w;
                acc[i][0] += av * bv.x;
                acc[i][1] += av * bv.y;
                acc[i][2] += av * bv.z;
                acc[i][3] += av * bv.w;
            }
        }
    }
#pragma unroll
    for (int i = 0; i < 4; i++) {
        int gr = row0 + ty * 4 + i;
        if (gr < n) {
            float4 v = make_float4(acc[i][0], acc[i][1], acc[i][2], acc[i][3]);
            *(float4*)(g_h1 + (size_t)gr * 64 + tx * 4) = v;
        }
    }
}

// ---------------- layer1 attention coefs + self-loop max init ----------------
__global__ void attn1_kernel(const float* __restrict__ att_src, const float* __restrict__ att_dst, int n) {
    int t = blockIdx.x * blockDim.x + threadIdx.x;
    if (t >= n * HEADS) return;
    int nidx = t >> 2, h = t & 3;
    const float* hp = g_h1 + (size_t)nidx * F1 + h * HID;
    float s = 0.f, d = 0.f;
#pragma unroll
    for (int c = 0; c < HID; c++) {
        float v = hp[c];
        s += v * att_src[h * HID + c];
        d += v * att_dst[h * HID + c];
    }
    g_as1[t] = s;
    g_ad1[t] = d;
    g_m1[t] = fenc(lrelu(s + d));   // self-loop edge value initializes the max
}

// ---------------- edge pass A (layer 1): segment max ----------------
__global__ void edgeA1_kernel(const int* __restrict__ ei, int E) {
    int e = blockIdx.x * blockDim.x + threadIdx.x;
    if (e >= E) return;
    int src = ei[e], dst = ei[(size_t)E + e];
    float4 as = *(const float4*)(g_as1 + (size_t)src * 4);
    float4 ad = *(const float4*)(g_ad1 + (size_t)dst * 4);
    atomicMax(g_m1 + (size_t)dst * 4 + 0, fenc(lrelu(as.x + ad.x)));
    atomicMax(g_m1 + (size_t)dst * 4 + 1, fenc(lrelu(as.y + ad.y)));
    atomicMax(g_m1 + (size_t)dst * 4 + 2, fenc(lrelu(as.z + ad.z)));
    atomicMax(g_m1 + (size_t)dst * 4 + 3, fenc(lrelu(as.w + ad.w)));
}

// ---------------- node mid (layer 1): decode max, init denom/accum with self-loop ----------------
__global__ void mid1_kernel(int n) {
    int t = blockIdx.x * blockDim.x + threadIdx.x;
    if (t >= n * HEADS) return;
    int nidx = t >> 2, h = t & 3;
    float eself = lrelu(g_as1[t] + g_ad1[t]);
    float m = fdec(g_m1[t]);
    ((float*)g_m1)[t] = m;                 // now holds float max
    float w = expf(eself - m);
    g_den1[t] = w;
    const float* hp = g_h1 + (size_t)nidx * F1 + h * HID;
    float* ap = g_acc1 + (size_t)nidx * F1 + h * HID;
#pragma unroll
    for (int c4 = 0; c4 < 4; c4++) {
        float4 v = *(const float4*)(hp + c4 * 4);
        float4 o = make_float4(w * v.x, w * v.y, w * v.z, w * v.w);
        *(float4*)(ap + c4 * 4) = o;
    }
}

// ---------------- edge pass B (layer 1): exp-sum + weighted message accumulation ----------------
__global__ void edgeB1_kernel(const int* __restrict__ ei, int E) {
    int e = blockIdx.x * blockDim.x + threadIdx.x;
    if (e >= E) return;
    int src = ei[e], dst = ei[(size_t)E + e];
    float4 as = *(const float4*)(g_as1 + (size_t)src * 4);
    float4 ad = *(const float4*)(g_ad1 + (size_t)dst * 4);
    const float* mf = (const float*)g_m1;
    float4 m = *(const float4*)(mf + (size_t)dst * 4);
    float ex[4];
    ex[0] = expf(lrelu(as.x + ad.x) - m.x);
    ex[1] = expf(lrelu(as.y + ad.y) - m.y);
    ex[2] = expf(lrelu(as.z + ad.z) - m.z);
    ex[3] = expf(lrelu(as.w + ad.w) - m.w);
    red_add_v4(g_den1 + (size_t)dst * 4, ex[0], ex[1], ex[2], ex[3]);
    const float* hp = g_h1 + (size_t)src * F1;
    float* ap = g_acc1 + (size_t)dst * F1;
#pragma unroll
    for (int h = 0; h < 4; h++) {
        float w = ex[h];
#pragma unroll
        for (int c4 = 0; c4 < 4; c4++) {
            float4 v = *(const float4*)(hp + h * HID + c4 * 4);
            red_add_v4(ap + h * HID + c4 * 4, w * v.x, w * v.y, w * v.z, w * v.w);
        }
    }
}

// ---------------- finalize layer 1: normalize + bias + ELU -> embeddings ----------------
__global__ void fin1_kernel(const float* __restrict__ b1, float* __restrict__ emb, int n) {
    int t = blockIdx.x * blockDim.x + threadIdx.x;
    if (t >= n * F1) return;
    int nidx = t >> 6, c = t & 63, h = c >> 4;
    float den = g_den1[nidx * 4 + h];
    float o = g_acc1[t] / fmaxf(den, 1e-16f) + b1[c];
    o = o > 0.f ? o : expm1f(o);
    emb[t] = o;
}

// ---------------- layer 2 GEMM: hw2 = emb @ W2  (N x 64 @ 64 x 16) ----------------
__global__ void gemm2_kernel(const float* __restrict__ emb, const float* __restrict__ W2, int n) {
    __shared__ float Es[16 * 64];
    __shared__ float Ws[64 * 16];
    int tid = threadIdx.x;
    int n0 = blockIdx.x * 16;
    for (int i = tid; i < 64 * 16; i += 256) Ws[i] = W2[i];
    for (int i = tid; i < 16 * 64; i += 256) {
        int r = i >> 6, c = i & 63;
        int gn = n0 + r;
        Es[i] = (gn < n) ? emb[(size_t)gn * 64 + c] : 0.f;
    }
    __syncthreads();
    int ni = tid >> 4, j = tid & 15;
    int gn = n0 + ni;
    if (gn >= n) return;
    float s = 0.f;
#pragma unroll
    for (int c = 0; c < 64; c++) s += Es[ni * 64 + c] * Ws[c * 16 + j];
    g_hw2[(size_t)gn * 16 + j] = s;
}

// ---------------- layer2 attention coefs + self-loop max init ----------------
__global__ void attn2_kernel(const float* __restrict__ att_src, const float* __restrict__ att_dst, int n) {
    int t = blockIdx.x * blockDim.x + threadIdx.x;
    if (t >= n) return;
    const float* hp = g_hw2 + (size_t)t * NC;
    float s = 0.f, d = 0.f;
#pragma unroll
    for (int j = 0; j < NC; j++) {
        float v = hp[j];
        s += v * att_src[j];
        d += v * att_dst[j];
    }
    g_as2[t] = s;
    g_ad2[t] = d;
    g_m2[t] = fenc(lrelu(s + d));
}

__global__ void edgeA2_kernel(const int* __restrict__ ei, int E) {
    int e = blockIdx.x * blockDim.x + threadIdx.x;
    if (e >= E) return;
    int src = ei[e], dst = ei[(size_t)E + e];
    atomicMax(g_m2 + dst, fenc(lrelu(g_as2[src] + g_ad2[dst])));
}

__global__ void mid2_kernel(int n) {
    int t = blockIdx.x * blockDim.x + threadIdx.x;
    if (t >= n) return;
    float eself = lrelu(g_as2[t] + g_ad2[t]);
    float m = fdec(g_m2[t]);
    ((float*)g_m2)[t] = m;
    float w = expf(eself - m);
    g_den2[t] = w;
    const float* hp = g_hw2 + (size_t)t * NC;
    float* ap = g_acc2 + (size_t)t * NC;
#pragma unroll
    for (int c4 = 0; c4 < 4; c4++) {
        float4 v = *(const float4*)(hp + c4 * 4);
        *(float4*)(ap + c4 * 4) = make_float4(w * v.x, w * v.y, w * v.z, w * v.w);
    }
}

__global__ void edgeB2_kernel(const int* __restrict__ ei, int E) {
    int e = blockIdx.x * blockDim.x + threadIdx.x;
    if (e >= E) return;
    int src = ei[e], dst = ei[(size_t)E + e];
    float m = ((const float*)g_m2)[dst];
    float ex = expf(lrelu(g_as2[src] + g_ad2[dst]) - m);
    atomicAdd(g_den2 + dst, ex);
    const float* hp = g_hw2 + (size_t)src * NC;
    float* ap = g_acc2 + (size_t)dst * NC;
#pragma unroll
    for (int c4 = 0; c4 < 4; c4++) {
        float4 v = *(const float4*)(hp + c4 * 4);
        red_add_v4(ap + c4 * 4, ex * v.x, ex * v.y, ex * v.z, ex * v.w);
    }
}

// ---------------- finalize layer 2: normalize + bias + log_softmax ----------------
__global__ void fin2_kernel(const float* __restrict__ b2, float* __restrict__ out, int n) {
    int t = blockIdx.x * blockDim.x + threadIdx.x;
    if (t >= n) return;
    float den = fmaxf(g_den2[t], 1e-16f);
    float l[NC];
    float mx = -1e30f;
#pragma unroll
    for (int j = 0; j < NC; j++) {
        l[j] = g_acc2[(size_t)t * NC + j] / den + b2[j];
        mx = fmaxf(mx, l[j]);
    }
    float sum = 0.f;
#pragma unroll
    for (int j = 0; j < NC; j++) sum += expf(l[j] - mx);
    float lse = mx + logf(sum);
    float* op = out + (size_t)t * NC;
#pragma unroll
    for (int j = 0; j < NC; j++) op[j] = l[j] - lse;
}

// ---------------- launch ----------------
extern "C" void kernel_launch(void* const* d_in, const int* in_sizes, int n_in,
                              void* d_out, int out_size) {
    const float* x        = (const float*)d_in[0];
    const int*   ei       = (const int*)d_in[1];     // int32! (JAX x64 disabled)
    const float* W1       = (const float*)d_in[2];
    const float* att_src1 = (const float*)d_in[3];
    const float* att_dst1 = (const float*)d_in[4];
    const float* b1       = (const float*)d_in[5];
    const float* W2       = (const float*)d_in[6];
    const float* att_src2 = (const float*)d_in[7];
    const float* att_dst2 = (const float*)d_in[8];
    const float* b2       = (const float*)d_in[9];

    int n = in_sizes[0] / 128;      // 100000
    int E = in_sizes[1] / 2;        // 1600000

    float* out_ls = (float*)d_out;                      // [n, 16] log-softmax
    float* emb    = (float*)d_out + (size_t)n * NC;     // [n, 64] embeddings

    cudaFuncSetAttribute(gemm1_kernel, cudaFuncAttributeMaxDynamicSharedMemorySize, 64 * 1024);

    int eb = (E + 255) / 256;

    gemm1_kernel<<<(n + 63) / 64, 256, 64 * 1024>>>(x, W1, n);
    attn1_kernel<<<(n * HEADS + 255) / 256, 256>>>(att_src1, att_dst1, n);
    edgeA1_kernel<<<eb, 256>>>(ei, E);
    mid1_kernel<<<(n * HEADS + 255) / 256, 256>>>(n);
    edgeB1_kernel<<<eb, 256>>>(ei, E);
    fin1_kernel<<<(n * F1 + 255) / 256, 256>>>(b1, emb, n);

    gemm2_kernel<<<(n + 15) / 16, 256>>>(emb, W2, n);
    attn2_kernel<<<(n + 255) / 256, 256>>>(att_src2, att_dst2, n);
    edgeA2_kernel<<<eb, 256>>>(ei, E);
    mid2_kernel<<<(n + 255) / 256, 256>>>(n);
    edgeB2_kernel<<<eb, 256>>>(ei, E);
    fin2_kernel<<<(n + 255) / 256, 256>>>(b2, out_ls, n);
}

// round 3
// speedup vs baseline: 1.2422x; 1.2422x over previous
#include <cuda_runtime.h>
#include <math.h>

#define NN 100000
#define EE 1600000
#define HEADS 4
#define HID 16
#define F1 64
#define NC 16
#define NEG 0.2f

// ---------------- scratch (device globals) ----------------
__device__ __align__(128) float g_h1[NN * F1];
__device__ __align__(128) float g_as1[NN * HEADS];
__device__ __align__(128) float g_ad1[NN * HEADS];
__device__ __align__(128) float g_hw2[NN * NC];
__device__ __align__(128) float g_as2[NN];
__device__ __align__(128) float g_ad2[NN];
__device__ __align__(128) int   g_cnt[NN];        // per-dst degree
__device__ __align__(128) int   g_offs[NN + 1];   // CSR offsets
__device__ __align__(128) int   g_cur[NN];        // scatter cursor
__device__ __align__(128) int   g_srcs[EE];       // src id grouped by dst

__device__ __forceinline__ float lrelu(float v) { return v >= 0.f ? v : NEG * v; }

// ---------------- CSR build ----------------
__global__ void zero_kernel(int n) {
    int t = blockIdx.x * blockDim.x + threadIdx.x;
    if (t < n) g_cnt[t] = 0;
}

__global__ void hist_kernel(const int* __restrict__ ei, int E) {
    int e = blockIdx.x * blockDim.x + threadIdx.x;
    if (e >= E) return;
    atomicAdd(&g_cnt[ei[(size_t)E + e]], 1);
}

__global__ void scan_kernel(int n) {
    __shared__ int sums[1024];
    int t = threadIdx.x;
    int per = (n + 1023) >> 10;
    int st = t * per, en = min(st + per, n);
    int s = 0;
    for (int i = st; i < en; i++) s += g_cnt[i];
    sums[t] = s;
    __syncthreads();
    for (int off = 1; off < 1024; off <<= 1) {
        int v = (t >= off) ? sums[t - off] : 0;
        __syncthreads();
        sums[t] += v;
        __syncthreads();
    }
    int run = (t == 0) ? 0 : sums[t - 1];
    for (int i = st; i < en; i++) {
        int c = g_cnt[i];
        g_offs[i] = run;
        g_cur[i] = run;
        run += c;
    }
    if (t == 1023) g_offs[n] = run;
}

__global__ void scatter_kernel(const int* __restrict__ ei, int E) {
    int e = blockIdx.x * blockDim.x + threadIdx.x;
    if (e >= E) return;
    int src = ei[e], dst = ei[(size_t)E + e];
    int pos = atomicAdd(&g_cur[dst], 1);
    g_srcs[pos] = src;
}

// ---------------- layer 1 GEMM: h1 = x @ W1 + attn coef epilogue ----------------
__global__ void gemm1_kernel(const float* __restrict__ x, const float* __restrict__ W1,
                             const float* __restrict__ att_src, const float* __restrict__ att_dst,
                             int n) {
    extern __shared__ float sm[];
    float* As = sm;               // 64 x 128
    float* Bs = sm + 64 * 128;    // 128 x 64
    int tid = threadIdx.x;
    int row0 = blockIdx.x * 64;

    for (int i = tid; i < 64 * 32; i += 256) {
        int r = i >> 5, c4 = (i & 31) << 2;
        float4 v = make_float4(0.f, 0.f, 0.f, 0.f);
        int gr = row0 + r;
        if (gr < n) v = *(const float4*)(x + (size_t)gr * 128 + c4);
        *(float4*)(As + r * 128 + c4) = v;
    }
    for (int i = tid; i < 128 * 16; i += 256) {
        int r = i >> 4, c4 = (i & 15) << 2;
        *(float4*)(Bs + r * 64 + c4) = *(const float4*)(W1 + r * 64 + c4);
    }
    __syncthreads();

    int tx = tid & 15, ty = tid >> 4;
    float acc[4][4];
#pragma unroll
    for (int i = 0; i < 4; i++)
#pragma unroll
        for (int j = 0; j < 4; j++) acc[i][j] = 0.f;

#pragma unroll
    for (int k4 = 0; k4 < 128; k4 += 4) {
        float4 a[4], b[4];
#pragma unroll
        for (int i = 0; i < 4; i++) a[i] = *(float4*)(As + (ty * 4 + i) * 128 + k4);
#pragma unroll
        for (int kk = 0; kk < 4; kk++) b[kk] = *(float4*)(Bs + (size_t)(k4 + kk) * 64 + tx * 4);
#pragma unroll
        for (int kk = 0; kk < 4; kk++) {
            float4 bv = b[kk];
#pragma unroll
            for (int i = 0; i < 4; i++) {
                float av = (kk == 0) ? a[i].x : (kk == 1) ? a[i].y : (kk == 2) ? a[i].z : a[i].w;
                acc[i][0] += av * bv.x;
                acc[i][1] += av * bv.y;
                acc[i][2] += av * bv.z;
                acc[i][3] += av * bv.w;
            }
        }
    }

    int head = tx >> 2;
    int coff = head * 16 + (tx & 3) * 4;
#pragma unroll
    for (int i = 0; i < 4; i++) {
        int gr = row0 + ty * 4 + i;
        if (gr < n) {
            *(float4*)(g_h1 + (size_t)gr * 64 + tx * 4) =
                make_float4(acc[i][0], acc[i][1], acc[i][2], acc[i][3]);
        }
        // attention coefficients (partial dot + 4-lane reduce)
        float ps = 0.f, pd = 0.f;
#pragma unroll
        for (int j = 0; j < 4; j++) {
            ps += acc[i][j] * att_src[coff + j];
            pd += acc[i][j] * att_dst[coff + j];
        }
        ps += __shfl_xor_sync(0xffffffffu, ps, 1);
        pd += __shfl_xor_sync(0xffffffffu, pd, 1);
        ps += __shfl_xor_sync(0xffffffffu, ps, 2);
        pd += __shfl_xor_sync(0xffffffffu, pd, 2);
        if ((tx & 3) == 0 && gr < n) {
            g_as1[(size_t)gr * 4 + head] = ps;
            g_ad1[(size_t)gr * 4 + head] = pd;
        }
    }
}

// ---------------- layer 1 aggregation: warp per dst node ----------------
// alpha without max subtraction (mathematically identical); self-loop included.
// Fuses normalize + bias + ELU -> writes embeddings directly.
__global__ void agg1_kernel(const float* __restrict__ b1, float* __restrict__ emb, int n) {
    int w = (blockIdx.x * blockDim.x + threadIdx.x) >> 5;
    if (w >= n) return;
    int lane = threadIdx.x & 31;
    int u = w;
    int h0 = lane >> 4;                 // head of channel c0=lane (0/1), c1=lane+32 -> head h0+2

    float4 ad4 = *(const float4*)(g_ad1 + (size_t)u * 4);
    float4 asu = *(const float4*)(g_as1 + (size_t)u * 4);

    // self-loop
    float exs0 = expf(lrelu(((h0 == 0) ? asu.x : asu.y) + ((h0 == 0) ? ad4.x : ad4.y)));
    float exs1 = expf(lrelu(((h0 == 0) ? asu.z : asu.w) + ((h0 == 0) ? ad4.z : ad4.w)));
    float acc0 = exs0 * g_h1[(size_t)u * 64 + lane];
    float acc1 = exs1 * g_h1[(size_t)u * 64 + 32 + lane];
    float den0 = exs0, den1 = exs1;

    int beg = g_offs[u], end = g_offs[u + 1];
    for (int base = beg; base < end; base += 32) {
        int idx = base + lane;
        int src = (idx < end) ? g_srcs[idx] : 0;
        float4 asv = *(const float4*)(g_as1 + (size_t)src * 4);
        float ex_x = expf(lrelu(asv.x + ad4.x));
        float ex_y = expf(lrelu(asv.y + ad4.y));
        float ex_z = expf(lrelu(asv.z + ad4.z));
        float ex_w = expf(lrelu(asv.w + ad4.w));
        int cnt = min(end - base, 32);
#pragma unroll 4
        for (int k = 0; k < cnt; k++) {
            int   sk  = __shfl_sync(0xffffffffu, src, k);
            float e0a = __shfl_sync(0xffffffffu, ex_x, k);
            float e0b = __shfl_sync(0xffffffffu, ex_y, k);
            float e1a = __shfl_sync(0xffffffffu, ex_z, k);
            float e1b = __shfl_sync(0xffffffffu, ex_w, k);
            float w0 = h0 ? e0b : e0a;
            float w1 = h0 ? e1b : e1a;
            float x0 = g_h1[(size_t)sk * 64 + lane];
            float x1 = g_h1[(size_t)sk * 64 + 32 + lane];
            acc0 = fmaf(w0, x0, acc0);
            acc1 = fmaf(w1, x1, acc1);
            den0 += w0;
            den1 += w1;
        }
    }
    float o0 = acc0 / fmaxf(den0, 1e-16f) + b1[lane];
    float o1 = acc1 / fmaxf(den1, 1e-16f) + b1[lane + 32];
    o0 = o0 > 0.f ? o0 : expm1f(o0);
    o1 = o1 > 0.f ? o1 : expm1f(o1);
    emb[(size_t)u * 64 + lane] = o0;
    emb[(size_t)u * 64 + 32 + lane] = o1;
}

// ---------------- layer 2 GEMM (N x 64 @ 64 x 16) + attn coef epilogue ----------------
__global__ void gemm2_kernel(const float* __restrict__ emb, const float* __restrict__ W2,
                             const float* __restrict__ att_src, const float* __restrict__ att_dst,
                             int n) {
    __shared__ float Es[16 * 64];
    __shared__ float Ws[64 * 16];
    int tid = threadIdx.x;
    int n0 = blockIdx.x * 16;
    for (int i = tid; i < 64 * 16; i += 256) Ws[i] = W2[i];
    for (int i = tid; i < 16 * 64; i += 256) {
        int r = i >> 6, c = i & 63;
        int gn = n0 + r;
        Es[i] = (gn < n) ? emb[(size_t)gn * 64 + c] : 0.f;
    }
    __syncthreads();
    int ni = tid >> 4, j = tid & 15;
    int gn = n0 + ni;
    float s = 0.f;
#pragma unroll
    for (int c = 0; c < 64; c++) s += Es[ni * 64 + c] * Ws[c * 16 + j];
    if (gn < n) g_hw2[(size_t)gn * 16 + j] = s;

    float ps = s * att_src[j], pd = s * att_dst[j];
#pragma unroll
    for (int o = 8; o; o >>= 1) {
        ps += __shfl_xor_sync(0xffffffffu, ps, o);
        pd += __shfl_xor_sync(0xffffffffu, pd, o);
    }
    if (j == 0 && gn < n) {
        g_as2[gn] = ps;
        g_ad2[gn] = pd;
    }
}

// ---------------- layer 2 aggregation + log_softmax: warp per dst node ----------------
__global__ void agg2_kernel(const float* __restrict__ b2, float* __restrict__ out, int n) {
    int w = (blockIdx.x * blockDim.x + threadIdx.x) >> 5;
    if (w >= n) return;
    int lane = threadIdx.x & 31;
    int u = w;
    int c = lane & 15;
    int half = lane >> 4;

    float ad = g_ad2[u];
    float exs = expf(lrelu(g_as2[u] + ad));
    float acc = 0.f, den = 0.f;
    if (half == 0) {
        acc = exs * g_hw2[(size_t)u * 16 + c];
        den = exs;
    }

    int beg = g_offs[u], end = g_offs[u + 1];
    for (int base = beg; base < end; base += 32) {
        int idx = base + lane;
        int src = (idx < end) ? g_srcs[idx] : 0;
        float ex = (idx < end) ? expf(lrelu(g_as2[src] + ad)) : 0.f;
        int cnt = min(end - base, 32);
#pragma unroll 4
        for (int k = 0; k < cnt; k += 2) {
            int kk = k + half;
            int   sk = __shfl_sync(0xffffffffu, src, kk & 31);
            float wv = __shfl_sync(0xffffffffu, ex, kk & 31);
            if (kk < cnt) {
                float x = g_hw2[(size_t)sk * 16 + c];
                acc = fmaf(wv, x, acc);
                den += wv;
            }
        }
    }
    acc += __shfl_xor_sync(0xffffffffu, acc, 16);
    den += __shfl_xor_sync(0xffffffffu, den, 16);

    float logit = acc / fmaxf(den, 1e-16f) + b2[c];
    float mx = logit;
#pragma unroll
    for (int o = 8; o; o >>= 1) mx = fmaxf(mx, __shfl_xor_sync(0xffffffffu, mx, o));
    float se = expf(logit - mx);
#pragma unroll
    for (int o = 8; o; o >>= 1) se += __shfl_xor_sync(0xffffffffu, se, o);
    float res = logit - (mx + logf(se));
    if (half == 0) out[(size_t)u * 16 + c] = res;
}

// ---------------- launch ----------------
extern "C" void kernel_launch(void* const* d_in, const int* in_sizes, int n_in,
                              void* d_out, int out_size) {
    const float* x        = (const float*)d_in[0];
    const int*   ei       = (const int*)d_in[1];
    const float* W1       = (const float*)d_in[2];
    const float* att_src1 = (const float*)d_in[3];
    const float* att_dst1 = (const float*)d_in[4];
    const float* b1       = (const float*)d_in[5];
    const float* W2       = (const float*)d_in[6];
    const float* att_src2 = (const float*)d_in[7];
    const float* att_dst2 = (const float*)d_in[8];
    const float* b2       = (const float*)d_in[9];

    int n = in_sizes[0] / 128;      // 100000
    int E = in_sizes[1] / 2;        // 1600000

    float* out_ls = (float*)d_out;
    float* emb    = (float*)d_out + (size_t)n * NC;

    cudaFuncSetAttribute(gemm1_kernel, cudaFuncAttributeMaxDynamicSharedMemorySize, 64 * 1024);

    int eb = (E + 255) / 256;
    int nb = (n + 255) / 256;
    int wb = (n * 32 + 255) / 256;   // warp-per-node grids

    // CSR build (shared by both layers)
    zero_kernel<<<nb, 256>>>(n);
    hist_kernel<<<eb, 256>>>(ei, E);
    scan_kernel<<<1, 1024>>>(n);
    scatter_kernel<<<eb, 256>>>(ei, E);

    // layer 1
    gemm1_kernel<<<(n + 63) / 64, 256, 64 * 1024>>>(x, W1, att_src1, att_dst1, n);
    agg1_kernel<<<wb, 256>>>(b1, emb, n);

    // layer 2
    gemm2_kernel<<<(n + 15) / 16, 256>>>(emb, W2, att_src2, att_dst2, n);
    agg2_kernel<<<wb, 256>>>(b2, out_ls, n);
}